// round 14
// baseline (speedup 1.0000x reference)
#include <cuda_runtime.h>

#define IMH 1024
#define IMW 1024
#define NTY 41
#define NTX 41
#define NDISP 169
#define NQ 82
#define TPW 1120   // padded tgt width: 48 | 1024 | 48

// ---------------- scratch (device globals; no allocation) ----------------
__device__ __align__(16) float g_tgtp[IMH * TPW];
__device__ __align__(16) float g_S[(size_t)NDISP * NQ * 1024];        // y-scanned rows per displacement
__device__ float g_cornersT[(size_t)NQ * NQ * NDISP];   // corners, displacement-minor
__device__ float g_bm[NTY * NTX * 2];                   // block-match grid (= -best_disp)
__device__ __align__(16) float2 g_r0[IMH * IMW];
__device__ __align__(16) float2 g_r1[IMH * IMW];

__device__ __forceinline__ float4 f4add(float4 a, float4 b) {
    float4 r;
    r.x = __fadd_rn(a.x, b.x);
    r.y = __fadd_rn(a.y, b.y);
    r.z = __fadd_rn(a.z, b.z);
    r.w = __fadd_rn(a.w, b.w);
    return r;
}

// ---------------- kernel 0: zero-padded tgt copy ----------------
__global__ void pad_tgt(const float* __restrict__ tgt) {
    int i = blockIdx.x * blockDim.x + threadIdx.x;
    if (i >= IMH * TPW) return;
    int y = i / TPW, x = i % TPW;
    int xs = x - 48;
    float v = 0.f;
    if (xs >= 0 && xs < IMW) v = tgt[y * IMW + xs];
    g_tgtp[i] = v;
}

// ---------------- kernel A: diff2 + aligned-dyadic column scan, dy-fused ----------------
// (round-5 validated version, bit-exact vs XLA associative_scan)
__global__ void __launch_bounds__(256) bm_colscan2(const float* __restrict__ src) {
    __shared__ float s_tgt[14][8][64];
    __shared__ float s_src[2][8][64];
    int tid = threadIdx.x;
    int bx  = blockIdx.x;          // 0..15 : src col block
    int dxi = blockIdx.y;          // 0..12
    int dx  = -48 + 8 * dxi;
    int qi  = tid & 15;
    int dyi = tid >> 4;            // 0..15; active when <13
    bool active = dyi < 13;
    int dyg = dyi - 6;             // tgt group offset (dy/8)
    int x = bx * 64 + qi * 4;
    int cbase = bx * 64 + 8 * dxi; // padded tgt col base (= x0 + dx + 48)

    float4 msk = make_float4(1.f, 1.f, 1.f, 1.f);
    bool allin = true;
    if (active) {
        float* mp = &msk.x;
        #pragma unroll
        for (int j = 0; j < 4; ++j) {
            int xt = x + j + dx;
            bool in = (xt >= 0) && (xt < IMW);
            mp[j] = in ? 1.f : 0.f;
            if (!in) allin = false;
        }
    }

    float* Sbase = nullptr;
    if (active) {
        int d = dyi * 13 + dxi;
        Sbase = &g_S[(size_t)d * NQ * 1024];
        *(float4*)&Sbase[x] = make_float4(0.f, 0.f, 0.f, 0.f);   // q=0 row
    }

    // prologue: tgt groups 0..6 into slots 0..6, src group 0 into buffer 0
    {
        int i = tid * 2, row = i >> 6, col = i & 63;
        #pragma unroll
        for (int gg = 0; gg < 7; ++gg)
            *(float2*)&s_tgt[gg][row][col] =
                *(const float2*)&g_tgtp[(gg * 8 + row) * TPW + cbase + col];
        *(float2*)&s_src[0][row][col] =
            *(const float2*)&src[row * IMW + bx * 64 + col];
    }
    __syncthreads();

    float4 acc[11];
    for (int g = 0; g < 128; ++g) {
        // prefetch tgt group g+7 (slot holds dead group g-7) and src g+1
        {
            int i = tid * 2, row = i >> 6, col = i & 63;
            int ggl = g + 7;
            if (ggl < 128)
                *(float2*)&s_tgt[ggl % 14][row][col] =
                    *(const float2*)&g_tgtp[(ggl * 8 + row) * TPW + cbase + col];
            if (g + 1 < 128)
                *(float2*)&s_src[(g + 1) & 1][row][col] =
                    *(const float2*)&src[((g + 1) * 8 + row) * IMW + bx * 64 + col];
        }

        if (active) {
            int gg = g + dyg;
            float4 v[8];
            if (gg >= 0 && gg < 128) {
                int slot = gg % 14;
                float4 s[8], t[8];
                #pragma unroll
                for (int k = 0; k < 8; ++k) s[k] = *(const float4*)&s_src[g & 1][k][qi * 4];
                #pragma unroll
                for (int k = 0; k < 8; ++k) t[k] = *(const float4*)&s_tgt[slot][k][qi * 4];
                #pragma unroll
                for (int k = 0; k < 8; ++k) {
                    float4 df, q;
                    df.x = __fsub_rn(s[k].x, t[k].x);
                    df.y = __fsub_rn(s[k].y, t[k].y);
                    df.z = __fsub_rn(s[k].z, t[k].z);
                    df.w = __fsub_rn(s[k].w, t[k].w);
                    q.x = __fmul_rn(df.x, df.x);
                    q.y = __fmul_rn(df.y, df.y);
                    q.z = __fmul_rn(df.z, df.z);
                    q.w = __fmul_rn(df.w, df.w);
                    if (!allin) {
                        q.x = __fmul_rn(q.x, msk.x);
                        q.y = __fmul_rn(q.y, msk.y);
                        q.z = __fmul_rn(q.z, msk.z);
                        q.w = __fmul_rn(q.w, msk.w);
                    }
                    v[k] = q;
                }
            } else {
                #pragma unroll
                for (int k = 0; k < 8; ++k) v[k] = make_float4(0.f, 0.f, 0.f, 0.f);
            }

            // binary-counter inserts, specialized for the 8-leaf subtree (verbatim)
            acc[0] = v[0];
            acc[1] = f4add(acc[0], v[1]);
            acc[0] = v[2];
            acc[2] = f4add(acc[1], f4add(acc[0], v[3]));
            acc[0] = v[4];
            acc[1] = f4add(acc[0], v[5]);
            acc[0] = v[6];
            float4 carry = f4add(acc[2], f4add(acc[1], f4add(acc[0], v[7])));
            {
                int tt = g, lvl = 3;
                while (tt & 1) { carry = f4add(acc[lvl], carry); tt >>= 1; ++lvl; }
                acc[lvl] = carry;
            }

            int m = g + 1;
            int row = -1;
            if (m % 3 == 0) { if (m <= 120) row = m / 3; }
            else if (m % 3 == 2) { if (m >= 8) row = 41 + (m - 8) / 3; }
            if (row >= 0) {
                float4 r = make_float4(0.f, 0.f, 0.f, 0.f);
                bool first = true;
                #pragma unroll
                for (int L = 10; L >= 3; --L) {
                    if ((m >> (L - 3)) & 1) { r = first ? acc[L] : f4add(r, acc[L]); first = false; }
                }
                *(float4*)&Sbase[row * 1024 + x] = r;
            }
        }
        __syncthreads();
    }
}

// ---------------- kernel B: row scan — upsweep only + dyadic fold ----------------
__global__ void bm_rowscan() {
    __shared__ float a[1024];
    int row = blockIdx.x;   // 0..81
    int d   = blockIdx.y;   // 0..168
    const float* Srow = &g_S[((size_t)d * NQ + row) * 1024];
    for (int i = threadIdx.x; i < 1024; i += blockDim.x) a[i] = Srow[i];
    __syncthreads();
    // upsweep only (10 rounds; same pairwise adds as the full Brent-Kung)
    for (int s = 1; s < 1024; s <<= 1) {
        for (int i = 2 * s - 1 + threadIdx.x * 2 * s; i < 1024; i += blockDim.x * 2 * s)
            a[i] = __fadd_rn(a[i - s], a[i]);
        __syncthreads();
    }
    if (threadIdx.x < NQ) {
        int j = threadIdx.x;
        int q = (j < 41) ? 24 * j : 64 + 24 * (j - 41);
        float r = 0.f;
        if (q > 0) {
            int pos = 0;
            bool first = true;
            #pragma unroll
            for (int L = 10; L >= 0; --L) {
                if ((q >> L) & 1) {
                    pos += (1 << L);
                    float b = a[pos - 1];
                    r = first ? b : __fadd_rn(r, b);
                    first = false;
                }
            }
        }
        g_cornersT[((size_t)row * NQ + j) * NDISP + d] = r;
    }
}

// ---------------- kernel C: per-tile argmin, parallel over displacements ----------------
__global__ void __launch_bounds__(256) bm_select() {
    __shared__ float sc[256];
    __shared__ int   sd[256];
    int t = blockIdx.x;
    int ty = t / NTX, tx = t % NTX;
    int y0 = ty * 24, x0 = tx * 24;
    int d = threadIdx.x;
    float cost = __int_as_float(0x7f800000);   // +inf
    if (d < NDISP) {
        int dy = -48 + 8 * (d / 13);
        int dx = -48 + 8 * (d % 13);
        float I11 = g_cornersT[((size_t)ty * NQ + tx) * NDISP + d];
        float I12 = g_cornersT[((size_t)ty * NQ + (41 + tx)) * NDISP + d];
        float I21 = g_cornersT[((size_t)(41 + ty) * NQ + tx) * NDISP + d];
        float I22 = g_cornersT[((size_t)(41 + ty) * NQ + (41 + tx)) * NDISP + d];
        float ssd = __fadd_rn(__fsub_rn(__fsub_rn(I22, I12), I21), I11);
        int cy = min(IMH, y0 + dy + 64) - max(0, y0 + dy); cy = max(cy, 0);
        int cx = min(IMW, x0 + dx + 64) - max(0, x0 + dx); cx = max(cx, 0);
        float cnt = (float)(cy * cx);
        cost = (cnt >= 500.f) ? __fdiv_rn(ssd, fmaxf(cnt, 1.f))
                              : __int_as_float(0x7f800000);
    }
    sc[threadIdx.x] = cost;
    sd[threadIdx.x] = d;
    __syncthreads();
    for (int ofs = 128; ofs > 0; ofs >>= 1) {
        if (threadIdx.x < ofs) {
            float c2 = sc[threadIdx.x + ofs];
            int   d2 = sd[threadIdx.x + ofs];
            if (c2 < sc[threadIdx.x] ||
                (c2 == sc[threadIdx.x] && d2 < sd[threadIdx.x])) {
                sc[threadIdx.x] = c2;
                sd[threadIdx.x] = d2;
            }
        }
        __syncthreads();
    }
    if (threadIdx.x == 0) {
        int bd = sd[0];
        float bdy = (float)(-48 + 8 * (bd / 13));
        float bdx = (float)(-48 + 8 * (bd % 13));
        g_bm[t * 2 + 0] = -bdy;   // grid = -best_disp
        g_bm[t * 2 + 1] = -bdx;
    }
}

// ---------------- kernel D: jax.image.resize 'bilinear' 41x41 -> 1024x1024 ----------------
__device__ __forceinline__ void resize_weights(int i, int& m0, int& m1, float& nw0, float& nw1) {
    const float inv = 0.0400390625f;  // 41/1024 exactly
    float sf = __fsub_rn(__fmul_rn(__fadd_rn((float)i, 0.5f), inv), 0.5f);
    int f0 = (int)floorf(sf);
    int f1 = f0 + 1;
    float w0 = 0.f, w1 = 0.f;
    if (f0 >= 0 && f0 <= 40) { float xx = fabsf(__fsub_rn(sf, (float)f0)); w0 = fmaxf(0.f, __fsub_rn(1.f, xx)); }
    if (f1 >= 0 && f1 <= 40) { float xx = fabsf(__fsub_rn(sf, (float)f1)); w1 = fmaxf(0.f, __fsub_rn(1.f, xx)); }
    float T = __fadd_rn(w0, w1);
    nw0 = __fdiv_rn(w0, T);
    nw1 = __fdiv_rn(w1, T);
    m0 = min(40, max(0, f0));
    m1 = min(40, max(0, f1));
}

__global__ void resize_init() {
    int Y = blockIdx.x;
    int my0, my1; float wy0, wy1;
    resize_weights(Y, my0, my1, wy0, wy1);
    for (int X = threadIdx.x; X < IMW; X += blockDim.x) {
        int mx0, mx1; float wx0, wx1;
        resize_weights(X, mx0, mx1, wx0, wx1);
        float o[2];
        #pragma unroll
        for (int c = 0; c < 2; ++c) {
            float g00 = g_bm[(my0 * NTX + mx0) * 2 + c];
            float g10 = g_bm[(my1 * NTX + mx0) * 2 + c];
            float g01 = g_bm[(my0 * NTX + mx1) * 2 + c];
            float g11 = g_bm[(my1 * NTX + mx1) * 2 + c];
            float t0 = __fadd_rn(__fmul_rn(wy0, g00), __fmul_rn(wy1, g10));
            float t1 = __fadd_rn(__fmul_rn(wy0, g01), __fmul_rn(wy1, g11));
            o[c]     = __fadd_rn(__fmul_rn(wx0, t0), __fmul_rn(wx1, t1));
        }
        g_r0[Y * IMW + X] = make_float2(o[0], o[1]);
    }
}

// ---------------- kernel E: one GD step, 2 horizontally-paired pixels/thread ----------------
// Per-pixel FP expressions verbatim from the validated rounds-3..8 kernels.
__device__ __forceinline__ float2 gd_math(float r0, float r1, int y, int x,
                                          float2 up, bool hu, float2 dn, bool hd,
                                          float2 lf, bool hl, float2 rt, bool hr,
                                          const float* __restrict__ src, float tgtv) {
    float sy = (float)y + r0;
    float sx = (float)x + r1;
    float y0f = floorf(sy), x0f = floorf(sx);
    float wy = sy - y0f, wx = sx - x0f;
    int y0 = min(IMH - 1, max(0, (int)y0f));
    int y1 = min(IMH - 1, y0 + 1);
    int x0 = min(IMW - 1, max(0, (int)x0f));
    int x1 = min(IMW - 1, x0 + 1);

    float v00 = src[y0 * IMW + x0];
    float v01 = src[y0 * IMW + x1];
    float v10 = src[y1 * IMW + x0];
    float v11 = src[y1 * IMW + x1];
    float omwy = 1.f - wy, omwx = 1.f - wx;
    float w = v00 * omwy * omwx + v01 * omwy * wx + v10 * wy * omwx + v11 * wy * wx;
    float diff = w - tgtv;
    float gy_ = 2.f * diff * ((v10 - v00) * omwx + (v11 - v01) * wx);
    float gx_ = 2.f * diff * ((v01 - v00) * omwy + (v11 - v10) * wy);

    float s0 = 0.f, s1 = 0.f;
    if (hu) { s0 += r0 - up.x; s1 += r1 - up.y; }
    if (hd) { s0 -= dn.x - r0; s1 -= dn.y - r1; }
    if (hl) { s0 += r0 - lf.x; s1 += r1 - lf.y; }
    if (hr) { s0 -= rt.x - r0; s1 -= rt.y - r1; }

    float o0 = r0 - 0.1f * (gy_ + 0.01f * (2.f * s0));
    float o1 = r1 - 0.1f * (gx_ + 0.01f * (2.f * s1));
    return make_float2(o0, o1);
}

__global__ void __launch_bounds__(256, 7) opt_step2(const float* __restrict__ src,
                                                    const float* __restrict__ tgt,
                                                    const float2* __restrict__ rin,
                                                    float2* __restrict__ rout,
                                                    float* __restrict__ finout) {
    // ---- preamble: everything independent of the previous step ----
    int x2 = (blockIdx.x * 32 + threadIdx.x) * 2;
    int y  = blockIdx.y * 8 + threadIdx.y;
    int p  = y * IMW + x2;
    bool hu = y > 0, hd = y < IMH - 1, hl = x2 > 0, hr = (x2 + 2) < IMW;
    float2 t2 = *(const float2*)&tgt[p];   // step-invariant input

    // ---- wait for the producing step's writes to be visible ----
#if __CUDA_ARCH__ >= 900
    cudaGridDependencySynchronize();
#endif

    float4 cen = *(const float4*)&rin[p];
    float4 up = make_float4(0.f, 0.f, 0.f, 0.f), dn = up;
    float2 lf = make_float2(0.f, 0.f), rt = lf;
    if (hu) up = *(const float4*)&rin[p - IMW];
    if (hd) dn = *(const float4*)&rin[p + IMW];
    if (hl) lf = rin[p - 1];
    if (hr) rt = rin[p + 2];

    float2 oA = gd_math(cen.x, cen.y, y, x2,
                        make_float2(up.x, up.y), hu, make_float2(dn.x, dn.y), hd,
                        lf, hl, make_float2(cen.z, cen.w), true, src, t2.x);
    float2 oB = gd_math(cen.z, cen.w, y, x2 + 1,
                        make_float2(up.z, up.w), hu, make_float2(dn.z, dn.w), hd,
                        make_float2(cen.x, cen.y), true, rt, hr, src, t2.y);

    if (finout) {
        // final step: fold in the exact *2/1024 (power-of-two, exact) scaling
        const float S = 0.001953125f;
        float4 o = make_float4(__fmul_rn(oA.x, S), __fmul_rn(oA.y, S),
                               __fmul_rn(oB.x, S), __fmul_rn(oB.y, S));
        *(float4*)&finout[2 * p] = o;
    } else {
        *(float4*)&rout[p] = make_float4(oA.x, oA.y, oB.x, oB.y);
    }

    // allow the next step's grid to begin dispatching while our tail drains
#if __CUDA_ARCH__ >= 900
    cudaTriggerProgrammaticLaunchCompletion();
#endif
}

extern "C" void kernel_launch(void* const* d_in, const int* in_sizes, int n_in,
                              void* d_out, int out_size) {
    const float* src = (const float*)d_in[0];
    const float* tgt = (const float*)d_in[1];
    float* out = (float*)d_out;

    // block matching
    pad_tgt<<<(IMH * TPW + 255) / 256, 256>>>(tgt);
    bm_colscan2<<<dim3(16, 13), 256>>>(src);
    bm_rowscan<<<dim3(NQ, NDISP), 512>>>();
    bm_select<<<NTY * NTX, 256>>>();

    // resize grid -> initial residual field
    resize_init<<<IMH, 256>>>();

    // 100 gradient-descent steps (ping-pong) with programmatic dependent launch
    static float2 *a0 = nullptr, *a1 = nullptr;
    if (!a0) {
        cudaGetSymbolAddress((void**)&a0, g_r0);
        cudaGetSymbolAddress((void**)&a1, g_r1);
    }

    cudaLaunchConfig_t cfg = {};
    cfg.gridDim  = dim3(IMW / 64, IMH / 8);
    cfg.blockDim = dim3(32, 8);
    cudaLaunchAttribute attrs[1];
    attrs[0].id = cudaLaunchAttributeProgrammaticStreamSerialization;
    attrs[0].val.programmaticStreamSerializationAllowed = 1;
    cfg.attrs = attrs;
    cfg.numAttrs = 1;

    for (int i = 0; i < 100; ++i) {
        const float2* rin = (i & 1) ? a1 : a0;
        float2* rout      = (i & 1) ? a0 : a1;
        float* fin        = (i == 99) ? out : nullptr;
        cudaLaunchKernelEx(&cfg, opt_step2, src, tgt, rin, rout, fin);
    }
}

// round 15
// speedup vs baseline: 1.0982x; 1.0982x over previous
#include <cuda_runtime.h>

#define IMH 1024
#define IMW 1024
#define NTY 41
#define NTX 41
#define NDISP 169
#define NQ 82
#define TPW 1120   // padded tgt width: 48 | 1024 | 48

// ---------------- scratch (device globals; no allocation) ----------------
__device__ __align__(16) float g_tgtp[IMH * TPW];
__device__ __align__(16) float g_S[(size_t)NDISP * NQ * 1024];        // y-scanned rows per displacement
__device__ float g_cornersT[(size_t)NQ * NQ * NDISP];   // corners, displacement-minor
__device__ float g_bm[NTY * NTX * 2];                   // block-match grid (= -best_disp)
__device__ __align__(16) float2 g_r0[IMH * IMW];
__device__ __align__(16) float2 g_r1[IMH * IMW];

__device__ __forceinline__ float4 f4add(float4 a, float4 b) {
    float4 r;
    r.x = __fadd_rn(a.x, b.x);
    r.y = __fadd_rn(a.y, b.y);
    r.z = __fadd_rn(a.z, b.z);
    r.w = __fadd_rn(a.w, b.w);
    return r;
}

#if defined(__CUDA_ARCH__) && __CUDA_ARCH__ >= 900
#define GDS()  cudaGridDependencySynchronize()
#define TRIG() cudaTriggerProgrammaticLaunchCompletion()
#else
#define GDS()
#define TRIG()
#endif

// ---------------- kernel 0: zero-padded tgt copy ----------------
__global__ void pad_tgt(const float* __restrict__ tgt) {
    int i = blockIdx.x * blockDim.x + threadIdx.x;
    if (i >= IMH * TPW) return;
    int y = i / TPW, x = i % TPW;
    int xs = x - 48;
    float v = 0.f;
    if (xs >= 0 && xs < IMW) v = tgt[y * IMW + xs];
    g_tgtp[i] = v;
    TRIG();
}

// ---------------- kernel A: diff2 + aligned-dyadic column scan, dy-fused ----------------
// (round-5 validated version, bit-exact vs XLA associative_scan)
__global__ void __launch_bounds__(256) bm_colscan2(const float* __restrict__ src) {
    __shared__ float s_tgt[14][8][64];
    __shared__ float s_src[2][8][64];
    int tid = threadIdx.x;
    int bx  = blockIdx.x;          // 0..15 : src col block
    int dxi = blockIdx.y;          // 0..12
    int dx  = -48 + 8 * dxi;
    int qi  = tid & 15;
    int dyi = tid >> 4;            // 0..15; active when <13
    bool active = dyi < 13;
    int dyg = dyi - 6;             // tgt group offset (dy/8)
    int x = bx * 64 + qi * 4;
    int cbase = bx * 64 + 8 * dxi; // padded tgt col base (= x0 + dx + 48)

    float4 msk = make_float4(1.f, 1.f, 1.f, 1.f);
    bool allin = true;
    if (active) {
        float* mp = &msk.x;
        #pragma unroll
        for (int j = 0; j < 4; ++j) {
            int xt = x + j + dx;
            bool in = (xt >= 0) && (xt < IMW);
            mp[j] = in ? 1.f : 0.f;
            if (!in) allin = false;
        }
    }

    float* Sbase = nullptr;
    if (active) {
        int d = dyi * 13 + dxi;
        Sbase = &g_S[(size_t)d * NQ * 1024];
        *(float4*)&Sbase[x] = make_float4(0.f, 0.f, 0.f, 0.f);   // q=0 row
    }

    // wait for pad_tgt's g_tgtp writes before the staging loads
    GDS();

    // prologue: tgt groups 0..6 into slots 0..6, src group 0 into buffer 0
    {
        int i = tid * 2, row = i >> 6, col = i & 63;
        #pragma unroll
        for (int gg = 0; gg < 7; ++gg)
            *(float2*)&s_tgt[gg][row][col] =
                *(const float2*)&g_tgtp[(gg * 8 + row) * TPW + cbase + col];
        *(float2*)&s_src[0][row][col] =
            *(const float2*)&src[row * IMW + bx * 64 + col];
    }
    __syncthreads();

    float4 acc[11];
    for (int g = 0; g < 128; ++g) {
        // prefetch tgt group g+7 (slot holds dead group g-7) and src g+1
        {
            int i = tid * 2, row = i >> 6, col = i & 63;
            int ggl = g + 7;
            if (ggl < 128)
                *(float2*)&s_tgt[ggl % 14][row][col] =
                    *(const float2*)&g_tgtp[(ggl * 8 + row) * TPW + cbase + col];
            if (g + 1 < 128)
                *(float2*)&s_src[(g + 1) & 1][row][col] =
                    *(const float2*)&src[((g + 1) * 8 + row) * IMW + bx * 64 + col];
        }

        if (active) {
            int gg = g + dyg;
            float4 v[8];
            if (gg >= 0 && gg < 128) {
                int slot = gg % 14;
                float4 s[8], t[8];
                #pragma unroll
                for (int k = 0; k < 8; ++k) s[k] = *(const float4*)&s_src[g & 1][k][qi * 4];
                #pragma unroll
                for (int k = 0; k < 8; ++k) t[k] = *(const float4*)&s_tgt[slot][k][qi * 4];
                #pragma unroll
                for (int k = 0; k < 8; ++k) {
                    float4 df, q;
                    df.x = __fsub_rn(s[k].x, t[k].x);
                    df.y = __fsub_rn(s[k].y, t[k].y);
                    df.z = __fsub_rn(s[k].z, t[k].z);
                    df.w = __fsub_rn(s[k].w, t[k].w);
                    q.x = __fmul_rn(df.x, df.x);
                    q.y = __fmul_rn(df.y, df.y);
                    q.z = __fmul_rn(df.z, df.z);
                    q.w = __fmul_rn(df.w, df.w);
                    if (!allin) {
                        q.x = __fmul_rn(q.x, msk.x);
                        q.y = __fmul_rn(q.y, msk.y);
                        q.z = __fmul_rn(q.z, msk.z);
                        q.w = __fmul_rn(q.w, msk.w);
                    }
                    v[k] = q;
                }
            } else {
                #pragma unroll
                for (int k = 0; k < 8; ++k) v[k] = make_float4(0.f, 0.f, 0.f, 0.f);
            }

            // binary-counter inserts, specialized for the 8-leaf subtree (verbatim)
            acc[0] = v[0];
            acc[1] = f4add(acc[0], v[1]);
            acc[0] = v[2];
            acc[2] = f4add(acc[1], f4add(acc[0], v[3]));
            acc[0] = v[4];
            acc[1] = f4add(acc[0], v[5]);
            acc[0] = v[6];
            float4 carry = f4add(acc[2], f4add(acc[1], f4add(acc[0], v[7])));
            {
                int tt = g, lvl = 3;
                while (tt & 1) { carry = f4add(acc[lvl], carry); tt >>= 1; ++lvl; }
                acc[lvl] = carry;
            }

            int m = g + 1;
            int row = -1;
            if (m % 3 == 0) { if (m <= 120) row = m / 3; }
            else if (m % 3 == 2) { if (m >= 8) row = 41 + (m - 8) / 3; }
            if (row >= 0) {
                float4 r = make_float4(0.f, 0.f, 0.f, 0.f);
                bool first = true;
                #pragma unroll
                for (int L = 10; L >= 3; --L) {
                    if ((m >> (L - 3)) & 1) { r = first ? acc[L] : f4add(r, acc[L]); first = false; }
                }
                *(float4*)&Sbase[row * 1024 + x] = r;
            }
        }
        __syncthreads();
    }
    TRIG();
}

// ---------------- kernel B: row scan — upsweep only + dyadic fold ----------------
__global__ void bm_rowscan() {
    __shared__ float a[1024];
    int row = blockIdx.x;   // 0..81
    int d   = blockIdx.y;   // 0..168
    const float* Srow = &g_S[((size_t)d * NQ + row) * 1024];
    GDS();   // wait for colscan's g_S
    for (int i = threadIdx.x; i < 1024; i += blockDim.x) a[i] = Srow[i];
    __syncthreads();
    // upsweep only (10 rounds; same pairwise adds as the full Brent-Kung)
    for (int s = 1; s < 1024; s <<= 1) {
        for (int i = 2 * s - 1 + threadIdx.x * 2 * s; i < 1024; i += blockDim.x * 2 * s)
            a[i] = __fadd_rn(a[i - s], a[i]);
        __syncthreads();
    }
    if (threadIdx.x < NQ) {
        int j = threadIdx.x;
        int q = (j < 41) ? 24 * j : 64 + 24 * (j - 41);
        float r = 0.f;
        if (q > 0) {
            int pos = 0;
            bool first = true;
            #pragma unroll
            for (int L = 10; L >= 0; --L) {
                if ((q >> L) & 1) {
                    pos += (1 << L);
                    float b = a[pos - 1];
                    r = first ? b : __fadd_rn(r, b);
                    first = false;
                }
            }
        }
        g_cornersT[((size_t)row * NQ + j) * NDISP + d] = r;
    }
    TRIG();
}

// ---------------- kernel C: per-tile argmin, parallel over displacements ----------------
__global__ void __launch_bounds__(256) bm_select() {
    __shared__ float sc[256];
    __shared__ int   sd[256];
    int t = blockIdx.x;
    int ty = t / NTX, tx = t % NTX;
    int y0 = ty * 24, x0 = tx * 24;
    int d = threadIdx.x;
    GDS();   // wait for rowscan's g_cornersT
    float cost = __int_as_float(0x7f800000);   // +inf
    if (d < NDISP) {
        int dy = -48 + 8 * (d / 13);
        int dx = -48 + 8 * (d % 13);
        float I11 = g_cornersT[((size_t)ty * NQ + tx) * NDISP + d];
        float I12 = g_cornersT[((size_t)ty * NQ + (41 + tx)) * NDISP + d];
        float I21 = g_cornersT[((size_t)(41 + ty) * NQ + tx) * NDISP + d];
        float I22 = g_cornersT[((size_t)(41 + ty) * NQ + (41 + tx)) * NDISP + d];
        float ssd = __fadd_rn(__fsub_rn(__fsub_rn(I22, I12), I21), I11);
        int cy = min(IMH, y0 + dy + 64) - max(0, y0 + dy); cy = max(cy, 0);
        int cx = min(IMW, x0 + dx + 64) - max(0, x0 + dx); cx = max(cx, 0);
        float cnt = (float)(cy * cx);
        cost = (cnt >= 500.f) ? __fdiv_rn(ssd, fmaxf(cnt, 1.f))
                              : __int_as_float(0x7f800000);
    }
    sc[threadIdx.x] = cost;
    sd[threadIdx.x] = d;
    __syncthreads();
    for (int ofs = 128; ofs > 0; ofs >>= 1) {
        if (threadIdx.x < ofs) {
            float c2 = sc[threadIdx.x + ofs];
            int   d2 = sd[threadIdx.x + ofs];
            if (c2 < sc[threadIdx.x] ||
                (c2 == sc[threadIdx.x] && d2 < sd[threadIdx.x])) {
                sc[threadIdx.x] = c2;
                sd[threadIdx.x] = d2;
            }
        }
        __syncthreads();
    }
    if (threadIdx.x == 0) {
        int bd = sd[0];
        float bdy = (float)(-48 + 8 * (bd / 13));
        float bdx = (float)(-48 + 8 * (bd % 13));
        g_bm[t * 2 + 0] = -bdy;   // grid = -best_disp
        g_bm[t * 2 + 1] = -bdx;
    }
    TRIG();
}

// ---------------- kernel D: jax.image.resize 'bilinear' 41x41 -> 1024x1024 ----------------
__device__ __forceinline__ void resize_weights(int i, int& m0, int& m1, float& nw0, float& nw1) {
    const float inv = 0.0400390625f;  // 41/1024 exactly
    float sf = __fsub_rn(__fmul_rn(__fadd_rn((float)i, 0.5f), inv), 0.5f);
    int f0 = (int)floorf(sf);
    int f1 = f0 + 1;
    float w0 = 0.f, w1 = 0.f;
    if (f0 >= 0 && f0 <= 40) { float xx = fabsf(__fsub_rn(sf, (float)f0)); w0 = fmaxf(0.f, __fsub_rn(1.f, xx)); }
    if (f1 >= 0 && f1 <= 40) { float xx = fabsf(__fsub_rn(sf, (float)f1)); w1 = fmaxf(0.f, __fsub_rn(1.f, xx)); }
    float T = __fadd_rn(w0, w1);
    nw0 = __fdiv_rn(w0, T);
    nw1 = __fdiv_rn(w1, T);
    m0 = min(40, max(0, f0));
    m1 = min(40, max(0, f1));
}

__global__ void resize_init() {
    int Y = blockIdx.x;
    int my0, my1; float wy0, wy1;
    resize_weights(Y, my0, my1, wy0, wy1);   // preamble: independent of g_bm
    GDS();   // wait for bm_select's g_bm
    for (int X = threadIdx.x; X < IMW; X += blockDim.x) {
        int mx0, mx1; float wx0, wx1;
        resize_weights(X, mx0, mx1, wx0, wx1);
        float o[2];
        #pragma unroll
        for (int c = 0; c < 2; ++c) {
            float g00 = g_bm[(my0 * NTX + mx0) * 2 + c];
            float g10 = g_bm[(my1 * NTX + mx0) * 2 + c];
            float g01 = g_bm[(my0 * NTX + mx1) * 2 + c];
            float g11 = g_bm[(my1 * NTX + mx1) * 2 + c];
            float t0 = __fadd_rn(__fmul_rn(wy0, g00), __fmul_rn(wy1, g10));
            float t1 = __fadd_rn(__fmul_rn(wy0, g01), __fmul_rn(wy1, g11));
            o[c]     = __fadd_rn(__fmul_rn(wx0, t0), __fmul_rn(wx1, t1));
        }
        g_r0[Y * IMW + X] = make_float2(o[0], o[1]);
    }
    TRIG();
}

// ---------------- kernel E: one GD step, 2 horizontally-paired pixels/thread ----------------
// Per-pixel FP expressions verbatim from the validated rounds-3..8 kernels.
__device__ __forceinline__ float2 gd_math(float r0, float r1, int y, int x,
                                          float2 up, bool hu, float2 dn, bool hd,
                                          float2 lf, bool hl, float2 rt, bool hr,
                                          const float* __restrict__ src, float tgtv) {
    float sy = (float)y + r0;
    float sx = (float)x + r1;
    float y0f = floorf(sy), x0f = floorf(sx);
    float wy = sy - y0f, wx = sx - x0f;
    int y0 = min(IMH - 1, max(0, (int)y0f));
    int y1 = min(IMH - 1, y0 + 1);
    int x0 = min(IMW - 1, max(0, (int)x0f));
    int x1 = min(IMW - 1, x0 + 1);

    float v00 = src[y0 * IMW + x0];
    float v01 = src[y0 * IMW + x1];
    float v10 = src[y1 * IMW + x0];
    float v11 = src[y1 * IMW + x1];
    float omwy = 1.f - wy, omwx = 1.f - wx;
    float w = v00 * omwy * omwx + v01 * omwy * wx + v10 * wy * omwx + v11 * wy * wx;
    float diff = w - tgtv;
    float gy_ = 2.f * diff * ((v10 - v00) * omwx + (v11 - v01) * wx);
    float gx_ = 2.f * diff * ((v01 - v00) * omwy + (v11 - v10) * wy);

    float s0 = 0.f, s1 = 0.f;
    if (hu) { s0 += r0 - up.x; s1 += r1 - up.y; }
    if (hd) { s0 -= dn.x - r0; s1 -= dn.y - r1; }
    if (hl) { s0 += r0 - lf.x; s1 += r1 - lf.y; }
    if (hr) { s0 -= rt.x - r0; s1 -= rt.y - r1; }

    float o0 = r0 - 0.1f * (gy_ + 0.01f * (2.f * s0));
    float o1 = r1 - 0.1f * (gx_ + 0.01f * (2.f * s1));
    return make_float2(o0, o1);
}

__global__ void __launch_bounds__(256, 6) opt_step2(const float* __restrict__ src,
                                                    const float* __restrict__ tgt,
                                                    const float2* __restrict__ rin,
                                                    float2* __restrict__ rout,
                                                    float* __restrict__ finout) {
    // ---- preamble: everything independent of the previous step ----
    int x2 = (blockIdx.x * 32 + threadIdx.x) * 2;
    int y  = blockIdx.y * 8 + threadIdx.y;
    int p  = y * IMW + x2;
    bool hu = y > 0, hd = y < IMH - 1, hl = x2 > 0, hr = (x2 + 2) < IMW;
    float2 t2 = *(const float2*)&tgt[p];   // step-invariant input

    // ---- wait for the producing step's writes to be visible ----
    GDS();

    float4 cen = *(const float4*)&rin[p];
    float4 up = make_float4(0.f, 0.f, 0.f, 0.f), dn = up;
    float2 lf = make_float2(0.f, 0.f), rt = lf;
    if (hu) up = *(const float4*)&rin[p - IMW];
    if (hd) dn = *(const float4*)&rin[p + IMW];
    if (hl) lf = rin[p - 1];
    if (hr) rt = rin[p + 2];

    float2 oA = gd_math(cen.x, cen.y, y, x2,
                        make_float2(up.x, up.y), hu, make_float2(dn.x, dn.y), hd,
                        lf, hl, make_float2(cen.z, cen.w), true, src, t2.x);
    float2 oB = gd_math(cen.z, cen.w, y, x2 + 1,
                        make_float2(up.z, up.w), hu, make_float2(dn.z, dn.w), hd,
                        make_float2(cen.x, cen.y), true, rt, hr, src, t2.y);

    if (finout) {
        // final step: fold in the exact *2/1024 (power-of-two, exact) scaling
        const float S = 0.001953125f;
        float4 o = make_float4(__fmul_rn(oA.x, S), __fmul_rn(oA.y, S),
                               __fmul_rn(oB.x, S), __fmul_rn(oB.y, S));
        *(float4*)&finout[2 * p] = o;
    } else {
        *(float4*)&rout[p] = make_float4(oA.x, oA.y, oB.x, oB.y);
    }

    // allow the next step's grid to begin dispatching while our tail drains
    TRIG();
}

extern "C" void kernel_launch(void* const* d_in, const int* in_sizes, int n_in,
                              void* d_out, int out_size) {
    const float* src = (const float*)d_in[0];
    const float* tgt = (const float*)d_in[1];
    float* out = (float*)d_out;

    cudaLaunchAttribute attrs[1];
    attrs[0].id = cudaLaunchAttributeProgrammaticStreamSerialization;
    attrs[0].val.programmaticStreamSerializationAllowed = 1;

    // block matching (PDL-chained prologue)
    pad_tgt<<<(IMH * TPW + 255) / 256, 256>>>(tgt);
    {
        cudaLaunchConfig_t c = {};
        c.gridDim = dim3(16, 13); c.blockDim = dim3(256);
        c.attrs = attrs; c.numAttrs = 1;
        cudaLaunchKernelEx(&c, bm_colscan2, src);
    }
    {
        cudaLaunchConfig_t c = {};
        c.gridDim = dim3(NQ, NDISP); c.blockDim = dim3(512);
        c.attrs = attrs; c.numAttrs = 1;
        cudaLaunchKernelEx(&c, bm_rowscan);
    }
    {
        cudaLaunchConfig_t c = {};
        c.gridDim = dim3(NTY * NTX); c.blockDim = dim3(256);
        c.attrs = attrs; c.numAttrs = 1;
        cudaLaunchKernelEx(&c, bm_select);
    }
    {
        cudaLaunchConfig_t c = {};
        c.gridDim = dim3(IMH); c.blockDim = dim3(256);
        c.attrs = attrs; c.numAttrs = 1;
        cudaLaunchKernelEx(&c, resize_init);
    }

    // 100 gradient-descent steps (ping-pong) with programmatic dependent launch
    static float2 *a0 = nullptr, *a1 = nullptr;
    if (!a0) {
        cudaGetSymbolAddress((void**)&a0, g_r0);
        cudaGetSymbolAddress((void**)&a1, g_r1);
    }

    cudaLaunchConfig_t cfg = {};
    cfg.gridDim  = dim3(IMW / 64, IMH / 8);
    cfg.blockDim = dim3(32, 8);
    cfg.attrs = attrs;
    cfg.numAttrs = 1;

    for (int i = 0; i < 100; ++i) {
        const float2* rin = (i & 1) ? a1 : a0;
        float2* rout      = (i & 1) ? a0 : a1;
        float* fin        = (i == 99) ? out : nullptr;
        cudaLaunchKernelEx(&cfg, opt_step2, src, tgt, rin, rout, fin);
    }
}

// round 16
// speedup vs baseline: 1.1039x; 1.0052x over previous
#include <cuda_runtime.h>

#define IMH 1024
#define IMW 1024
#define NTY 41
#define NTX 41
#define NDISP 169
#define NQ 82

// ---------------- scratch (device globals; no allocation) ----------------
__device__ __align__(16) float g_S[(size_t)NDISP * NQ * 1024];        // y-scanned rows per displacement
__device__ float g_cornersT[(size_t)NQ * NQ * NDISP];   // corners, displacement-minor
__device__ float g_bm[NTY * NTX * 2];                   // block-match grid (= -best_disp)
__device__ __align__(16) float2 g_r0[IMH * IMW];
__device__ __align__(16) float2 g_r1[IMH * IMW];

__device__ __forceinline__ float4 f4add(float4 a, float4 b) {
    float4 r;
    r.x = __fadd_rn(a.x, b.x);
    r.y = __fadd_rn(a.y, b.y);
    r.z = __fadd_rn(a.z, b.z);
    r.w = __fadd_rn(a.w, b.w);
    return r;
}

// ---------------- kernel A: diff2 + aligned-dyadic column scan, dy-fused ----------------
// (round-5 validated structure, bit-exact vs XLA associative_scan)
// pad_tgt folded in: staging loads read tgt directly with exact zero fill for
// out-of-range columns — byte-identical smem contents to the old padded buffer.
__global__ void __launch_bounds__(256) bm_colscan2(const float* __restrict__ src,
                                                   const float* __restrict__ tgt) {
    __shared__ float s_tgt[14][8][64];
    __shared__ float s_src[2][8][64];
    int tid = threadIdx.x;
    int bx  = blockIdx.x;          // 0..15 : src col block
    int dxi = blockIdx.y;          // 0..12
    int dx  = -48 + 8 * dxi;
    int qi  = tid & 15;
    int dyi = tid >> 4;            // 0..15; active when <13
    bool active = dyi < 13;
    int dyg = dyi - 6;             // tgt group offset (dy/8)
    int x = bx * 64 + qi * 4;
    int cb = bx * 64 + 8 * dxi - 48;   // real tgt column of staged col 0 (may be OOB)

    float4 msk = make_float4(1.f, 1.f, 1.f, 1.f);
    bool allin = true;
    if (active) {
        float* mp = &msk.x;
        #pragma unroll
        for (int j = 0; j < 4; ++j) {
            int xt = x + j + dx;
            bool in = (xt >= 0) && (xt < IMW);
            mp[j] = in ? 1.f : 0.f;
            if (!in) allin = false;
        }
    }

    float* Sbase = nullptr;
    if (active) {
        int d = dyi * 13 + dxi;
        Sbase = &g_S[(size_t)d * NQ * 1024];
        *(float4*)&Sbase[x] = make_float4(0.f, 0.f, 0.f, 0.f);   // q=0 row
    }

    // staging coords: each thread stages 2 consecutive cols of one row
    int strow = (tid * 2) >> 6;        // 0..7
    int stcol = (tid * 2) & 63;        // 0,2,..,62
    int xt0 = cb + stcol;
    int xt1 = cb + stcol + 1;
    bool in0 = (xt0 >= 0) && (xt0 < IMW);
    bool in1 = (xt1 >= 0) && (xt1 < IMW);

    // prologue: tgt groups 0..6 into slots 0..6, src group 0 into buffer 0
    {
        #pragma unroll
        for (int gg = 0; gg < 7; ++gg) {
            int rowbase = (gg * 8 + strow) * IMW;
            s_tgt[gg][strow][stcol]     = in0 ? tgt[rowbase + xt0] : 0.f;
            s_tgt[gg][strow][stcol + 1] = in1 ? tgt[rowbase + xt1] : 0.f;
        }
        *(float2*)&s_src[0][strow][stcol] =
            *(const float2*)&src[strow * IMW + bx * 64 + stcol];
    }
    __syncthreads();

    float4 acc[11];
    for (int g = 0; g < 128; ++g) {
        // prefetch tgt group g+7 (slot holds dead group g-7) and src g+1
        {
            int ggl = g + 7;
            if (ggl < 128) {
                int slot = ggl % 14;
                int rowbase = (ggl * 8 + strow) * IMW;
                s_tgt[slot][strow][stcol]     = in0 ? tgt[rowbase + xt0] : 0.f;
                s_tgt[slot][strow][stcol + 1] = in1 ? tgt[rowbase + xt1] : 0.f;
            }
            if (g + 1 < 128)
                *(float2*)&s_src[(g + 1) & 1][strow][stcol] =
                    *(const float2*)&src[((g + 1) * 8 + strow) * IMW + bx * 64 + stcol];
        }

        if (active) {
            int gg = g + dyg;
            float4 v[8];
            if (gg >= 0 && gg < 128) {
                int slot = gg % 14;
                float4 s[8], t[8];
                #pragma unroll
                for (int k = 0; k < 8; ++k) s[k] = *(const float4*)&s_src[g & 1][k][qi * 4];
                #pragma unroll
                for (int k = 0; k < 8; ++k) t[k] = *(const float4*)&s_tgt[slot][k][qi * 4];
                #pragma unroll
                for (int k = 0; k < 8; ++k) {
                    float4 df, q;
                    df.x = __fsub_rn(s[k].x, t[k].x);
                    df.y = __fsub_rn(s[k].y, t[k].y);
                    df.z = __fsub_rn(s[k].z, t[k].z);
                    df.w = __fsub_rn(s[k].w, t[k].w);
                    q.x = __fmul_rn(df.x, df.x);
                    q.y = __fmul_rn(df.y, df.y);
                    q.z = __fmul_rn(df.z, df.z);
                    q.w = __fmul_rn(df.w, df.w);
                    if (!allin) {
                        q.x = __fmul_rn(q.x, msk.x);
                        q.y = __fmul_rn(q.y, msk.y);
                        q.z = __fmul_rn(q.z, msk.z);
                        q.w = __fmul_rn(q.w, msk.w);
                    }
                    v[k] = q;
                }
            } else {
                #pragma unroll
                for (int k = 0; k < 8; ++k) v[k] = make_float4(0.f, 0.f, 0.f, 0.f);
            }

            // binary-counter inserts, specialized for the 8-leaf subtree (verbatim)
            acc[0] = v[0];
            acc[1] = f4add(acc[0], v[1]);
            acc[0] = v[2];
            acc[2] = f4add(acc[1], f4add(acc[0], v[3]));
            acc[0] = v[4];
            acc[1] = f4add(acc[0], v[5]);
            acc[0] = v[6];
            float4 carry = f4add(acc[2], f4add(acc[1], f4add(acc[0], v[7])));
            {
                int tt = g, lvl = 3;
                while (tt & 1) { carry = f4add(acc[lvl], carry); tt >>= 1; ++lvl; }
                acc[lvl] = carry;
            }

            int m = g + 1;
            int row = -1;
            if (m % 3 == 0) { if (m <= 120) row = m / 3; }
            else if (m % 3 == 2) { if (m >= 8) row = 41 + (m - 8) / 3; }
            if (row >= 0) {
                float4 r = make_float4(0.f, 0.f, 0.f, 0.f);
                bool first = true;
                #pragma unroll
                for (int L = 10; L >= 3; --L) {
                    if ((m >> (L - 3)) & 1) { r = first ? acc[L] : f4add(r, acc[L]); first = false; }
                }
                *(float4*)&Sbase[row * 1024 + x] = r;
            }
        }
        __syncthreads();
    }
}

// ---------------- kernel B: row scan — upsweep only + dyadic fold ----------------
__global__ void bm_rowscan() {
    __shared__ float a[1024];
    int row = blockIdx.x;   // 0..81
    int d   = blockIdx.y;   // 0..168
    const float* Srow = &g_S[((size_t)d * NQ + row) * 1024];
    for (int i = threadIdx.x; i < 1024; i += blockDim.x) a[i] = Srow[i];
    __syncthreads();
    // upsweep only (10 rounds; same pairwise adds as the full Brent-Kung)
    for (int s = 1; s < 1024; s <<= 1) {
        for (int i = 2 * s - 1 + threadIdx.x * 2 * s; i < 1024; i += blockDim.x * 2 * s)
            a[i] = __fadd_rn(a[i - s], a[i]);
        __syncthreads();
    }
    if (threadIdx.x < NQ) {
        int j = threadIdx.x;
        int q = (j < 41) ? 24 * j : 64 + 24 * (j - 41);
        float r = 0.f;
        if (q > 0) {
            int pos = 0;
            bool first = true;
            #pragma unroll
            for (int L = 10; L >= 0; --L) {
                if ((q >> L) & 1) {
                    pos += (1 << L);
                    float b = a[pos - 1];
                    r = first ? b : __fadd_rn(r, b);
                    first = false;
                }
            }
        }
        g_cornersT[((size_t)row * NQ + j) * NDISP + d] = r;
    }
}

// ---------------- kernel C: per-tile argmin, parallel over displacements ----------------
__global__ void __launch_bounds__(256) bm_select() {
    __shared__ float sc[256];
    __shared__ int   sd[256];
    int t = blockIdx.x;
    int ty = t / NTX, tx = t % NTX;
    int y0 = ty * 24, x0 = tx * 24;
    int d = threadIdx.x;
    float cost = __int_as_float(0x7f800000);   // +inf
    if (d < NDISP) {
        int dy = -48 + 8 * (d / 13);
        int dx = -48 + 8 * (d % 13);
        float I11 = g_cornersT[((size_t)ty * NQ + tx) * NDISP + d];
        float I12 = g_cornersT[((size_t)ty * NQ + (41 + tx)) * NDISP + d];
        float I21 = g_cornersT[((size_t)(41 + ty) * NQ + tx) * NDISP + d];
        float I22 = g_cornersT[((size_t)(41 + ty) * NQ + (41 + tx)) * NDISP + d];
        float ssd = __fadd_rn(__fsub_rn(__fsub_rn(I22, I12), I21), I11);
        int cy = min(IMH, y0 + dy + 64) - max(0, y0 + dy); cy = max(cy, 0);
        int cx = min(IMW, x0 + dx + 64) - max(0, x0 + dx); cx = max(cx, 0);
        float cnt = (float)(cy * cx);
        cost = (cnt >= 500.f) ? __fdiv_rn(ssd, fmaxf(cnt, 1.f))
                              : __int_as_float(0x7f800000);
    }
    sc[threadIdx.x] = cost;
    sd[threadIdx.x] = d;
    __syncthreads();
    for (int ofs = 128; ofs > 0; ofs >>= 1) {
        if (threadIdx.x < ofs) {
            float c2 = sc[threadIdx.x + ofs];
            int   d2 = sd[threadIdx.x + ofs];
            if (c2 < sc[threadIdx.x] ||
                (c2 == sc[threadIdx.x] && d2 < sd[threadIdx.x])) {
                sc[threadIdx.x] = c2;
                sd[threadIdx.x] = d2;
            }
        }
        __syncthreads();
    }
    if (threadIdx.x == 0) {
        int bd = sd[0];
        float bdy = (float)(-48 + 8 * (bd / 13));
        float bdx = (float)(-48 + 8 * (bd % 13));
        g_bm[t * 2 + 0] = -bdy;   // grid = -best_disp
        g_bm[t * 2 + 1] = -bdx;
    }
}

// ---------------- kernel D: jax.image.resize 'bilinear' 41x41 -> 1024x1024 ----------------
__device__ __forceinline__ void resize_weights(int i, int& m0, int& m1, float& nw0, float& nw1) {
    const float inv = 0.0400390625f;  // 41/1024 exactly
    float sf = __fsub_rn(__fmul_rn(__fadd_rn((float)i, 0.5f), inv), 0.5f);
    int f0 = (int)floorf(sf);
    int f1 = f0 + 1;
    float w0 = 0.f, w1 = 0.f;
    if (f0 >= 0 && f0 <= 40) { float xx = fabsf(__fsub_rn(sf, (float)f0)); w0 = fmaxf(0.f, __fsub_rn(1.f, xx)); }
    if (f1 >= 0 && f1 <= 40) { float xx = fabsf(__fsub_rn(sf, (float)f1)); w1 = fmaxf(0.f, __fsub_rn(1.f, xx)); }
    float T = __fadd_rn(w0, w1);
    nw0 = __fdiv_rn(w0, T);
    nw1 = __fdiv_rn(w1, T);
    m0 = min(40, max(0, f0));
    m1 = min(40, max(0, f1));
}

__global__ void resize_init() {
    int Y = blockIdx.x;
    int my0, my1; float wy0, wy1;
    resize_weights(Y, my0, my1, wy0, wy1);
    for (int X = threadIdx.x; X < IMW; X += blockDim.x) {
        int mx0, mx1; float wx0, wx1;
        resize_weights(X, mx0, mx1, wx0, wx1);
        float o[2];
        #pragma unroll
        for (int c = 0; c < 2; ++c) {
            float g00 = g_bm[(my0 * NTX + mx0) * 2 + c];
            float g10 = g_bm[(my1 * NTX + mx0) * 2 + c];
            float g01 = g_bm[(my0 * NTX + mx1) * 2 + c];
            float g11 = g_bm[(my1 * NTX + mx1) * 2 + c];
            float t0 = __fadd_rn(__fmul_rn(wy0, g00), __fmul_rn(wy1, g10));
            float t1 = __fadd_rn(__fmul_rn(wy0, g01), __fmul_rn(wy1, g11));
            o[c]     = __fadd_rn(__fmul_rn(wx0, t0), __fmul_rn(wx1, t1));
        }
        g_r0[Y * IMW + X] = make_float2(o[0], o[1]);
    }
}

// ---------------- kernel E: one GD step, 2 horizontally-paired pixels/thread ----------------
// Per-pixel FP expressions verbatim from the validated rounds-3..8 kernels.
__device__ __forceinline__ float2 gd_math(float r0, float r1, int y, int x,
                                          float2 up, bool hu, float2 dn, bool hd,
                                          float2 lf, bool hl, float2 rt, bool hr,
                                          const float* __restrict__ src, float tgtv) {
    float sy = (float)y + r0;
    float sx = (float)x + r1;
    float y0f = floorf(sy), x0f = floorf(sx);
    float wy = sy - y0f, wx = sx - x0f;
    int y0 = min(IMH - 1, max(0, (int)y0f));
    int y1 = min(IMH - 1, y0 + 1);
    int x0 = min(IMW - 1, max(0, (int)x0f));
    int x1 = min(IMW - 1, x0 + 1);

    float v00 = src[y0 * IMW + x0];
    float v01 = src[y0 * IMW + x1];
    float v10 = src[y1 * IMW + x0];
    float v11 = src[y1 * IMW + x1];
    float omwy = 1.f - wy, omwx = 1.f - wx;
    float w = v00 * omwy * omwx + v01 * omwy * wx + v10 * wy * omwx + v11 * wy * wx;
    float diff = w - tgtv;
    float gy_ = 2.f * diff * ((v10 - v00) * omwx + (v11 - v01) * wx);
    float gx_ = 2.f * diff * ((v01 - v00) * omwy + (v11 - v10) * wy);

    float s0 = 0.f, s1 = 0.f;
    if (hu) { s0 += r0 - up.x; s1 += r1 - up.y; }
    if (hd) { s0 -= dn.x - r0; s1 -= dn.y - r1; }
    if (hl) { s0 += r0 - lf.x; s1 += r1 - lf.y; }
    if (hr) { s0 -= rt.x - r0; s1 -= rt.y - r1; }

    float o0 = r0 - 0.1f * (gy_ + 0.01f * (2.f * s0));
    float o1 = r1 - 0.1f * (gx_ + 0.01f * (2.f * s1));
    return make_float2(o0, o1);
}

__global__ void __launch_bounds__(256, 6) opt_step2(const float* __restrict__ src,
                                                    const float* __restrict__ tgt,
                                                    const float2* __restrict__ rin,
                                                    float2* __restrict__ rout,
                                                    float* __restrict__ finout) {
    // ---- preamble: everything independent of the previous step ----
    int x2 = (blockIdx.x * 32 + threadIdx.x) * 2;
    int y  = blockIdx.y * 8 + threadIdx.y;
    int p  = y * IMW + x2;
    bool hu = y > 0, hd = y < IMH - 1, hl = x2 > 0, hr = (x2 + 2) < IMW;
    float2 t2 = *(const float2*)&tgt[p];   // step-invariant input

    // ---- wait for the producing step's writes to be visible ----
#if __CUDA_ARCH__ >= 900
    cudaGridDependencySynchronize();
#endif

    float4 cen = *(const float4*)&rin[p];
    float4 up = make_float4(0.f, 0.f, 0.f, 0.f), dn = up;
    float2 lf = make_float2(0.f, 0.f), rt = lf;
    if (hu) up = *(const float4*)&rin[p - IMW];
    if (hd) dn = *(const float4*)&rin[p + IMW];
    if (hl) lf = rin[p - 1];
    if (hr) rt = rin[p + 2];

    float2 oA = gd_math(cen.x, cen.y, y, x2,
                        make_float2(up.x, up.y), hu, make_float2(dn.x, dn.y), hd,
                        lf, hl, make_float2(cen.z, cen.w), true, src, t2.x);
    float2 oB = gd_math(cen.z, cen.w, y, x2 + 1,
                        make_float2(up.z, up.w), hu, make_float2(dn.z, dn.w), hd,
                        make_float2(cen.x, cen.y), true, rt, hr, src, t2.y);

    if (finout) {
        // final step: fold in the exact *2/1024 (power-of-two, exact) scaling
        const float S = 0.001953125f;
        float4 o = make_float4(__fmul_rn(oA.x, S), __fmul_rn(oA.y, S),
                               __fmul_rn(oB.x, S), __fmul_rn(oB.y, S));
        *(float4*)&finout[2 * p] = o;
    } else {
        *(float4*)&rout[p] = make_float4(oA.x, oA.y, oB.x, oB.y);
    }

    // allow the next step's grid to begin dispatching while our tail drains
#if __CUDA_ARCH__ >= 900
    cudaTriggerProgrammaticLaunchCompletion();
#endif
}

extern "C" void kernel_launch(void* const* d_in, const int* in_sizes, int n_in,
                              void* d_out, int out_size) {
    const float* src = (const float*)d_in[0];
    const float* tgt = (const float*)d_in[1];
    float* out = (float*)d_out;

    // block matching (pad_tgt folded into colscan staging)
    bm_colscan2<<<dim3(16, 13), 256>>>(src, tgt);
    bm_rowscan<<<dim3(NQ, NDISP), 512>>>();
    bm_select<<<NTY * NTX, 256>>>();

    // resize grid -> initial residual field
    resize_init<<<IMH, 256>>>();

    // 100 gradient-descent steps (ping-pong) with programmatic dependent launch
    static float2 *a0 = nullptr, *a1 = nullptr;
    if (!a0) {
        cudaGetSymbolAddress((void**)&a0, g_r0);
        cudaGetSymbolAddress((void**)&a1, g_r1);
    }

    cudaLaunchConfig_t cfg = {};
    cfg.gridDim  = dim3(IMW / 64, IMH / 8);
    cfg.blockDim = dim3(32, 8);
    cudaLaunchAttribute attrs[1];
    attrs[0].id = cudaLaunchAttributeProgrammaticStreamSerialization;
    attrs[0].val.programmaticStreamSerializationAllowed = 1;
    cfg.attrs = attrs;
    cfg.numAttrs = 1;

    for (int i = 0; i < 100; ++i) {
        const float2* rin = (i & 1) ? a1 : a0;
        float2* rout      = (i & 1) ? a0 : a1;
        float* fin        = (i == 99) ? out : nullptr;
        cudaLaunchKernelEx(&cfg, opt_step2, src, tgt, rin, rout, fin);
    }
}

// round 17
// speedup vs baseline: 1.1183x; 1.0131x over previous
#include <cuda_runtime.h>

#define IMH 1024
#define IMW 1024
#define NTY 41
#define NTX 41
#define NDISP 169
#define NQ 82

// ---------------- scratch (device globals; no allocation) ----------------
__device__ __align__(16) float g_S[(size_t)NDISP * NQ * 1024];        // y-scanned rows per displacement
__device__ float g_cornersT[(size_t)NQ * NQ * NDISP];   // corners, displacement-minor
__device__ float g_bm[NTY * NTX * 2];                   // block-match grid (= -best_disp)
__device__ __align__(16) float2 g_r0[IMH * IMW];
__device__ __align__(16) float2 g_r1[IMH * IMW];

__device__ __forceinline__ float4 f4add(float4 a, float4 b) {
    float4 r;
    r.x = __fadd_rn(a.x, b.x);
    r.y = __fadd_rn(a.y, b.y);
    r.z = __fadd_rn(a.z, b.z);
    r.w = __fadd_rn(a.w, b.w);
    return r;
}

// ---------------- kernel A: diff2 + aligned-dyadic column scan, dy-fused ----------------
// (round-15 champion version: pad_tgt folded into staging, bit-exact vs XLA)
__global__ void __launch_bounds__(256) bm_colscan2(const float* __restrict__ src,
                                                   const float* __restrict__ tgt) {
    __shared__ float s_tgt[14][8][64];
    __shared__ float s_src[2][8][64];
    int tid = threadIdx.x;
    int bx  = blockIdx.x;          // 0..15 : src col block
    int dxi = blockIdx.y;          // 0..12
    int dx  = -48 + 8 * dxi;
    int qi  = tid & 15;
    int dyi = tid >> 4;            // 0..15; active when <13
    bool active = dyi < 13;
    int dyg = dyi - 6;             // tgt group offset (dy/8)
    int x = bx * 64 + qi * 4;
    int cb = bx * 64 + 8 * dxi - 48;   // real tgt column of staged col 0 (may be OOB)

    float4 msk = make_float4(1.f, 1.f, 1.f, 1.f);
    bool allin = true;
    if (active) {
        float* mp = &msk.x;
        #pragma unroll
        for (int j = 0; j < 4; ++j) {
            int xt = x + j + dx;
            bool in = (xt >= 0) && (xt < IMW);
            mp[j] = in ? 1.f : 0.f;
            if (!in) allin = false;
        }
    }

    float* Sbase = nullptr;
    if (active) {
        int d = dyi * 13 + dxi;
        Sbase = &g_S[(size_t)d * NQ * 1024];
        *(float4*)&Sbase[x] = make_float4(0.f, 0.f, 0.f, 0.f);   // q=0 row
    }

    // staging coords: each thread stages 2 consecutive cols of one row
    int strow = (tid * 2) >> 6;        // 0..7
    int stcol = (tid * 2) & 63;        // 0,2,..,62
    int xt0 = cb + stcol;
    int xt1 = cb + stcol + 1;
    bool in0 = (xt0 >= 0) && (xt0 < IMW);
    bool in1 = (xt1 >= 0) && (xt1 < IMW);

    // prologue: tgt groups 0..6 into slots 0..6, src group 0 into buffer 0
    {
        #pragma unroll
        for (int gg = 0; gg < 7; ++gg) {
            int rowbase = (gg * 8 + strow) * IMW;
            s_tgt[gg][strow][stcol]     = in0 ? tgt[rowbase + xt0] : 0.f;
            s_tgt[gg][strow][stcol + 1] = in1 ? tgt[rowbase + xt1] : 0.f;
        }
        *(float2*)&s_src[0][strow][stcol] =
            *(const float2*)&src[strow * IMW + bx * 64 + stcol];
    }
    __syncthreads();

    float4 acc[11];
    for (int g = 0; g < 128; ++g) {
        // prefetch tgt group g+7 (slot holds dead group g-7) and src g+1
        {
            int ggl = g + 7;
            if (ggl < 128) {
                int slot = ggl % 14;
                int rowbase = (ggl * 8 + strow) * IMW;
                s_tgt[slot][strow][stcol]     = in0 ? tgt[rowbase + xt0] : 0.f;
                s_tgt[slot][strow][stcol + 1] = in1 ? tgt[rowbase + xt1] : 0.f;
            }
            if (g + 1 < 128)
                *(float2*)&s_src[(g + 1) & 1][strow][stcol] =
                    *(const float2*)&src[((g + 1) * 8 + strow) * IMW + bx * 64 + stcol];
        }

        if (active) {
            int gg = g + dyg;
            float4 v[8];
            if (gg >= 0 && gg < 128) {
                int slot = gg % 14;
                float4 s[8], t[8];
                #pragma unroll
                for (int k = 0; k < 8; ++k) s[k] = *(const float4*)&s_src[g & 1][k][qi * 4];
                #pragma unroll
                for (int k = 0; k < 8; ++k) t[k] = *(const float4*)&s_tgt[slot][k][qi * 4];
                #pragma unroll
                for (int k = 0; k < 8; ++k) {
                    float4 df, q;
                    df.x = __fsub_rn(s[k].x, t[k].x);
                    df.y = __fsub_rn(s[k].y, t[k].y);
                    df.z = __fsub_rn(s[k].z, t[k].z);
                    df.w = __fsub_rn(s[k].w, t[k].w);
                    q.x = __fmul_rn(df.x, df.x);
                    q.y = __fmul_rn(df.y, df.y);
                    q.z = __fmul_rn(df.z, df.z);
                    q.w = __fmul_rn(df.w, df.w);
                    if (!allin) {
                        q.x = __fmul_rn(q.x, msk.x);
                        q.y = __fmul_rn(q.y, msk.y);
                        q.z = __fmul_rn(q.z, msk.z);
                        q.w = __fmul_rn(q.w, msk.w);
                    }
                    v[k] = q;
                }
            } else {
                #pragma unroll
                for (int k = 0; k < 8; ++k) v[k] = make_float4(0.f, 0.f, 0.f, 0.f);
            }

            // binary-counter inserts, specialized for the 8-leaf subtree (verbatim)
            acc[0] = v[0];
            acc[1] = f4add(acc[0], v[1]);
            acc[0] = v[2];
            acc[2] = f4add(acc[1], f4add(acc[0], v[3]));
            acc[0] = v[4];
            acc[1] = f4add(acc[0], v[5]);
            acc[0] = v[6];
            float4 carry = f4add(acc[2], f4add(acc[1], f4add(acc[0], v[7])));
            {
                int tt = g, lvl = 3;
                while (tt & 1) { carry = f4add(acc[lvl], carry); tt >>= 1; ++lvl; }
                acc[lvl] = carry;
            }

            int m = g + 1;
            int row = -1;
            if (m % 3 == 0) { if (m <= 120) row = m / 3; }
            else if (m % 3 == 2) { if (m >= 8) row = 41 + (m - 8) / 3; }
            if (row >= 0) {
                float4 r = make_float4(0.f, 0.f, 0.f, 0.f);
                bool first = true;
                #pragma unroll
                for (int L = 10; L >= 3; --L) {
                    if ((m >> (L - 3)) & 1) { r = first ? acc[L] : f4add(r, acc[L]); first = false; }
                }
                *(float4*)&Sbase[row * 1024 + x] = r;
            }
        }
        __syncthreads();
    }
}

// ---------------- kernel B: row scan — upsweep only + dyadic fold, 2 rows/block ----------------
// Identical pairwise adds in the identical tree order as the validated 1-row
// version; only the thread->add mapping and block shape change -> bit-exact.
__global__ void __launch_bounds__(512) bm_rowscan2() {
    __shared__ float a[2][1024];
    int pair = blockIdx.x;   // 0..40  (rows 2*pair, 2*pair+1)
    int d    = blockIdx.y;   // 0..168
    int t    = threadIdx.x;  // 0..511
    int tr   = t >> 8;       // sub-row 0/1
    int tt   = t & 255;      // thread index within sub-row

    // stage both rows (coalesced: consecutive t -> consecutive columns)
    const float* Sbase = &g_S[((size_t)d * NQ + 2 * pair) * 1024];
    for (int i = t; i < 2048; i += 512)
        a[i >> 10][i & 1023] = Sbase[i];
    __syncthreads();

    // upsweep, both rows concurrently (256 threads per row)
    for (int s = 1; s < 1024; s <<= 1) {
        for (int i = 2 * s - 1 + tt * 2 * s; i < 1024; i += 256 * 2 * s)
            a[tr][i] = __fadd_rn(a[tr][i - s], a[tr][i]);
        __syncthreads();
    }

    // dyadic fold: 82 outputs per row (verbatim association)
    if (tt < NQ) {
        int j = tt;
        int q = (j < 41) ? 24 * j : 64 + 24 * (j - 41);
        float r = 0.f;
        if (q > 0) {
            int pos = 0;
            bool first = true;
            #pragma unroll
            for (int L = 10; L >= 0; --L) {
                if ((q >> L) & 1) {
                    pos += (1 << L);
                    float b = a[tr][pos - 1];
                    r = first ? b : __fadd_rn(r, b);
                    first = false;
                }
            }
        }
        int row = 2 * pair + tr;
        g_cornersT[((size_t)row * NQ + j) * NDISP + d] = r;
    }
}

// ---------------- kernel C: per-tile argmin, parallel over displacements ----------------
__global__ void __launch_bounds__(256) bm_select() {
    __shared__ float sc[256];
    __shared__ int   sd[256];
    int t = blockIdx.x;
    int ty = t / NTX, tx = t % NTX;
    int y0 = ty * 24, x0 = tx * 24;
    int d = threadIdx.x;
    float cost = __int_as_float(0x7f800000);   // +inf
    if (d < NDISP) {
        int dy = -48 + 8 * (d / 13);
        int dx = -48 + 8 * (d % 13);
        float I11 = g_cornersT[((size_t)ty * NQ + tx) * NDISP + d];
        float I12 = g_cornersT[((size_t)ty * NQ + (41 + tx)) * NDISP + d];
        float I21 = g_cornersT[((size_t)(41 + ty) * NQ + tx) * NDISP + d];
        float I22 = g_cornersT[((size_t)(41 + ty) * NQ + (41 + tx)) * NDISP + d];
        float ssd = __fadd_rn(__fsub_rn(__fsub_rn(I22, I12), I21), I11);
        int cy = min(IMH, y0 + dy + 64) - max(0, y0 + dy); cy = max(cy, 0);
        int cx = min(IMW, x0 + dx + 64) - max(0, x0 + dx); cx = max(cx, 0);
        float cnt = (float)(cy * cx);
        cost = (cnt >= 500.f) ? __fdiv_rn(ssd, fmaxf(cnt, 1.f))
                              : __int_as_float(0x7f800000);
    }
    sc[threadIdx.x] = cost;
    sd[threadIdx.x] = d;
    __syncthreads();
    for (int ofs = 128; ofs > 0; ofs >>= 1) {
        if (threadIdx.x < ofs) {
            float c2 = sc[threadIdx.x + ofs];
            int   d2 = sd[threadIdx.x + ofs];
            if (c2 < sc[threadIdx.x] ||
                (c2 == sc[threadIdx.x] && d2 < sd[threadIdx.x])) {
                sc[threadIdx.x] = c2;
                sd[threadIdx.x] = d2;
            }
        }
        __syncthreads();
    }
    if (threadIdx.x == 0) {
        int bd = sd[0];
        float bdy = (float)(-48 + 8 * (bd / 13));
        float bdx = (float)(-48 + 8 * (bd % 13));
        g_bm[t * 2 + 0] = -bdy;   // grid = -best_disp
        g_bm[t * 2 + 1] = -bdx;
    }
}

// ---------------- kernel D: jax.image.resize 'bilinear' 41x41 -> 1024x1024 ----------------
__device__ __forceinline__ void resize_weights(int i, int& m0, int& m1, float& nw0, float& nw1) {
    const float inv = 0.0400390625f;  // 41/1024 exactly
    float sf = __fsub_rn(__fmul_rn(__fadd_rn((float)i, 0.5f), inv), 0.5f);
    int f0 = (int)floorf(sf);
    int f1 = f0 + 1;
    float w0 = 0.f, w1 = 0.f;
    if (f0 >= 0 && f0 <= 40) { float xx = fabsf(__fsub_rn(sf, (float)f0)); w0 = fmaxf(0.f, __fsub_rn(1.f, xx)); }
    if (f1 >= 0 && f1 <= 40) { float xx = fabsf(__fsub_rn(sf, (float)f1)); w1 = fmaxf(0.f, __fsub_rn(1.f, xx)); }
    float T = __fadd_rn(w0, w1);
    nw0 = __fdiv_rn(w0, T);
    nw1 = __fdiv_rn(w1, T);
    m0 = min(40, max(0, f0));
    m1 = min(40, max(0, f1));
}

__global__ void resize_init() {
    int Y = blockIdx.x;
    int my0, my1; float wy0, wy1;
    resize_weights(Y, my0, my1, wy0, wy1);
    for (int X = threadIdx.x; X < IMW; X += blockDim.x) {
        int mx0, mx1; float wx0, wx1;
        resize_weights(X, mx0, mx1, wx0, wx1);
        float o[2];
        #pragma unroll
        for (int c = 0; c < 2; ++c) {
            float g00 = g_bm[(my0 * NTX + mx0) * 2 + c];
            float g10 = g_bm[(my1 * NTX + mx0) * 2 + c];
            float g01 = g_bm[(my0 * NTX + mx1) * 2 + c];
            float g11 = g_bm[(my1 * NTX + mx1) * 2 + c];
            float t0 = __fadd_rn(__fmul_rn(wy0, g00), __fmul_rn(wy1, g10));
            float t1 = __fadd_rn(__fmul_rn(wy0, g01), __fmul_rn(wy1, g11));
            o[c]     = __fadd_rn(__fmul_rn(wx0, t0), __fmul_rn(wx1, t1));
        }
        g_r0[Y * IMW + X] = make_float2(o[0], o[1]);
    }
}

// ---------------- kernel E: one GD step, 2 horizontally-paired pixels/thread ----------------
// Per-pixel FP expressions verbatim from the validated rounds-3..8 kernels.
__device__ __forceinline__ float2 gd_math(float r0, float r1, int y, int x,
                                          float2 up, bool hu, float2 dn, bool hd,
                                          float2 lf, bool hl, float2 rt, bool hr,
                                          const float* __restrict__ src, float tgtv) {
    float sy = (float)y + r0;
    float sx = (float)x + r1;
    float y0f = floorf(sy), x0f = floorf(sx);
    float wy = sy - y0f, wx = sx - x0f;
    int y0 = min(IMH - 1, max(0, (int)y0f));
    int y1 = min(IMH - 1, y0 + 1);
    int x0 = min(IMW - 1, max(0, (int)x0f));
    int x1 = min(IMW - 1, x0 + 1);

    float v00 = src[y0 * IMW + x0];
    float v01 = src[y0 * IMW + x1];
    float v10 = src[y1 * IMW + x0];
    float v11 = src[y1 * IMW + x1];
    float omwy = 1.f - wy, omwx = 1.f - wx;
    float w = v00 * omwy * omwx + v01 * omwy * wx + v10 * wy * omwx + v11 * wy * wx;
    float diff = w - tgtv;
    float gy_ = 2.f * diff * ((v10 - v00) * omwx + (v11 - v01) * wx);
    float gx_ = 2.f * diff * ((v01 - v00) * omwy + (v11 - v10) * wy);

    float s0 = 0.f, s1 = 0.f;
    if (hu) { s0 += r0 - up.x; s1 += r1 - up.y; }
    if (hd) { s0 -= dn.x - r0; s1 -= dn.y - r1; }
    if (hl) { s0 += r0 - lf.x; s1 += r1 - lf.y; }
    if (hr) { s0 -= rt.x - r0; s1 -= rt.y - r1; }

    float o0 = r0 - 0.1f * (gy_ + 0.01f * (2.f * s0));
    float o1 = r1 - 0.1f * (gx_ + 0.01f * (2.f * s1));
    return make_float2(o0, o1);
}

__global__ void __launch_bounds__(256, 6) opt_step2(const float* __restrict__ src,
                                                    const float* __restrict__ tgt,
                                                    const float2* __restrict__ rin,
                                                    float2* __restrict__ rout,
                                                    float* __restrict__ finout) {
    // ---- preamble: everything independent of the previous step ----
    int x2 = (blockIdx.x * 32 + threadIdx.x) * 2;
    int y  = blockIdx.y * 8 + threadIdx.y;
    int p  = y * IMW + x2;
    bool hu = y > 0, hd = y < IMH - 1, hl = x2 > 0, hr = (x2 + 2) < IMW;
    float2 t2 = *(const float2*)&tgt[p];   // step-invariant input

    // ---- wait for the producing step's writes to be visible ----
#if __CUDA_ARCH__ >= 900
    cudaGridDependencySynchronize();
#endif

    float4 cen = *(const float4*)&rin[p];
    float4 up = make_float4(0.f, 0.f, 0.f, 0.f), dn = up;
    float2 lf = make_float2(0.f, 0.f), rt = lf;
    if (hu) up = *(const float4*)&rin[p - IMW];
    if (hd) dn = *(const float4*)&rin[p + IMW];
    if (hl) lf = rin[p - 1];
    if (hr) rt = rin[p + 2];

    float2 oA = gd_math(cen.x, cen.y, y, x2,
                        make_float2(up.x, up.y), hu, make_float2(dn.x, dn.y), hd,
                        lf, hl, make_float2(cen.z, cen.w), true, src, t2.x);
    float2 oB = gd_math(cen.z, cen.w, y, x2 + 1,
                        make_float2(up.z, up.w), hu, make_float2(dn.z, dn.w), hd,
                        make_float2(cen.x, cen.y), true, rt, hr, src, t2.y);

    if (finout) {
        // final step: fold in the exact *2/1024 (power-of-two, exact) scaling
        const float S = 0.001953125f;
        float4 o = make_float4(__fmul_rn(oA.x, S), __fmul_rn(oA.y, S),
                               __fmul_rn(oB.x, S), __fmul_rn(oB.y, S));
        *(float4*)&finout[2 * p] = o;
    } else {
        *(float4*)&rout[p] = make_float4(oA.x, oA.y, oB.x, oB.y);
    }

    // allow the next step's grid to begin dispatching while our tail drains
#if __CUDA_ARCH__ >= 900
    cudaTriggerProgrammaticLaunchCompletion();
#endif
}

extern "C" void kernel_launch(void* const* d_in, const int* in_sizes, int n_in,
                              void* d_out, int out_size) {
    const float* src = (const float*)d_in[0];
    const float* tgt = (const float*)d_in[1];
    float* out = (float*)d_out;

    // block matching (pad_tgt folded into colscan staging)
    bm_colscan2<<<dim3(16, 13), 256>>>(src, tgt);
    bm_rowscan2<<<dim3(NQ / 2, NDISP), 512>>>();
    bm_select<<<NTY * NTX, 256>>>();

    // resize grid -> initial residual field
    resize_init<<<IMH, 256>>>();

    // 100 gradient-descent steps (ping-pong) with programmatic dependent launch
    static float2 *a0 = nullptr, *a1 = nullptr;
    if (!a0) {
        cudaGetSymbolAddress((void**)&a0, g_r0);
        cudaGetSymbolAddress((void**)&a1, g_r1);
    }

    cudaLaunchConfig_t cfg = {};
    cfg.gridDim  = dim3(IMW / 64, IMH / 8);
    cfg.blockDim = dim3(32, 8);
    cudaLaunchAttribute attrs[1];
    attrs[0].id = cudaLaunchAttributeProgrammaticStreamSerialization;
    attrs[0].val.programmaticStreamSerializationAllowed = 1;
    cfg.attrs = attrs;
    cfg.numAttrs = 1;

    for (int i = 0; i < 100; ++i) {
        const float2* rin = (i & 1) ? a1 : a0;
        float2* rout      = (i & 1) ? a0 : a1;
        float* fin        = (i == 99) ? out : nullptr;
        cudaLaunchKernelEx(&cfg, opt_step2, src, tgt, rin, rout, fin);
    }
}